// round 11
// baseline (speedup 1.0000x reference)
#include <cuda_runtime.h>
#include <stdint.h>
#include <math.h>

// Problem constants
#define BB 4
#define SS 2048
#define DD 1024
#define HH 16
#define DK 64
#define MM (BB * SS)                  // 8192 rows for projections
#define OUT0 ((size_t)BB * SS * DD)   // offset of attn in d_out (elements)

// Scratch (device globals)
__device__ __align__(16) float g_Qp[MM * DD];
__device__ __align__(16) float g_Kp[MM * DD];
__device__ __align__(16) float g_Vp[MM * DD];
__device__ float g_rinv[(size_t)BB * HH * SS];

// Pre-split planes (bf16x2 hi/lo packed along k-pairs)
#define APW (MM * DD / 2)
#define WPW (DD * DD / 2)
__device__ __align__(16) uint32_t g_xh[APW], g_xl[APW];
__device__ __align__(16) uint32_t g_wqh[WPW], g_wql[WPW];
__device__ __align__(16) uint32_t g_wkh[WPW], g_wkl[WPW];
__device__ __align__(16) uint32_t g_wvh[WPW], g_wvl[WPW];
__device__ __align__(16) uint32_t g_woh[WPW], g_wol[WPW];

// ---------------------------------------------------------------------------
// bf16x3 helpers
// ---------------------------------------------------------------------------
__device__ __forceinline__ void bfsplit2(float x0, float x1,
                                         uint32_t& hi, uint32_t& lo) {
    asm("cvt.rn.bf16x2.f32 %0, %1, %2;" : "=r"(hi) : "f"(x1), "f"(x0));
    float h0 = __uint_as_float(hi << 16);
    float h1 = __uint_as_float(hi & 0xffff0000u);
    asm("cvt.rn.bf16x2.f32 %0, %1, %2;" : "=r"(lo) : "f"(x1 - h1), "f"(x0 - h0));
}
__device__ __forceinline__ void mma16(float* c,
                                      uint32_t a0, uint32_t a1, uint32_t a2, uint32_t a3,
                                      uint32_t b0, uint32_t b1) {
    asm volatile(
        "mma.sync.aligned.m16n8k16.row.col.f32.bf16.bf16.f32 "
        "{%0,%1,%2,%3}, {%4,%5,%6,%7}, {%8,%9}, {%0,%1,%2,%3};"
        : "+f"(c[0]), "+f"(c[1]), "+f"(c[2]), "+f"(c[3])
        : "r"(a0), "r"(a1), "r"(a2), "r"(a3), "r"(b0), "r"(b1));
}
__device__ __forceinline__ void cpasync16(void* smem, const void* gmem) {
    uint32_t sa = (uint32_t)__cvta_generic_to_shared(smem);
    asm volatile("cp.async.cg.shared.global [%0], [%1], 16;" :: "r"(sa), "l"(gmem));
}

// ---------------------------------------------------------------------------
// Prep: split fp32 -> packed bf16x2 hi/lo planes (weights only; cheap).
// ---------------------------------------------------------------------------
__global__ __launch_bounds__(256) void split_pack(
    const float* __restrict__ src, uint32_t* __restrict__ hp,
    uint32_t* __restrict__ lp, int nquads)
{
    int q = blockIdx.x * 256 + threadIdx.x;
    if (q >= nquads) return;
    float4 v = ((const float4*)src)[q];
    uint32_t h0, l0, h1, l1;
    bfsplit2(v.x, v.y, h0, l0);
    bfsplit2(v.z, v.w, h1, l1);
    ((uint2*)hp)[q] = make_uint2(h0, h1);
    ((uint2*)lp)[q] = make_uint2(l0, l1);
}

// ---------------------------------------------------------------------------
// QKV batched GEMM (bf16x3): z selects (A, W-planes, bias, C).  (R8-proven)
// ---------------------------------------------------------------------------
#define QALD 24
#define QKP 12
#define QKV_SMEM_BYTES 49152

__global__ __launch_bounds__(256, 2) void gemm_qkv(
    const float* __restrict__ Aq, const float* __restrict__ Ak,
    const float* __restrict__ Av,
    const float* __restrict__ bq, const float* __restrict__ bk,
    const float* __restrict__ bv,
    float* __restrict__ Cq, float* __restrict__ Ck, float* __restrict__ Cv)
{
    extern __shared__ uint32_t qsm[];
    float*    AsS = (float*)qsm;
    uint32_t* BhS = qsm + 2 * 128 * QALD;
    uint32_t* BlS = BhS + 2 * 128 * QKP;

    const int K = DD, N = DD, Kp = DD / 2;
    const float* A; const uint32_t* Wh; const uint32_t* Wl;
    const float* bias; float* C;
    if (blockIdx.z == 0)      { A = Aq; Wh = g_wqh; Wl = g_wql; bias = bq; C = Cq; }
    else if (blockIdx.z == 1) { A = Ak; Wh = g_wkh; Wl = g_wkl; bias = bk; C = Ck; }
    else                      { A = Av; Wh = g_wvh; Wl = g_wvl; bias = bv; C = Cv; }

    const int bm = blockIdx.y * 128, bn = blockIdx.x * 128;
    const int tid = threadIdx.x, lane = tid & 31, warp = tid >> 5;
    const int wm = (warp >> 2) * 64, wn = (warp & 3) * 32;
    const int g = lane >> 2, tg = lane & 3;

    const int lrowA = tid >> 2, kkA = (tid & 3) * 4;
    const float* a0p = A + (size_t)(bm + lrowA) * K + kkA;
    const float* a1p = A + (size_t)(bm + lrowA + 64) * K + kkA;
    const int rowB = tid >> 1, offB = (tid & 1) * 4;
    const uint32_t* bhp = Wh + (size_t)(bn + rowB) * Kp + offB;
    const uint32_t* blp = Wl + (size_t)(bn + rowB) * Kp + offB;

    float acc[4][4][4];
#pragma unroll
    for (int mt = 0; mt < 4; mt++)
#pragma unroll
        for (int nt = 0; nt < 4; nt++)
#pragma unroll
            for (int r = 0; r < 4; r++) acc[mt][nt][r] = 0.f;

    const int nk = K / 16;

#define QKV_ISSUE(stage, it_)                                                 \
    {                                                                         \
        float*    as = AsS + (stage) * 128 * QALD;                            \
        uint32_t* bh = BhS + (stage) * 128 * QKP;                             \
        uint32_t* bl = BlS + (stage) * 128 * QKP;                             \
        cpasync16(as + lrowA * QALD + kkA,        a0p + (it_) * 16);          \
        cpasync16(as + (lrowA + 64) * QALD + kkA, a1p + (it_) * 16);          \
        cpasync16(bh + rowB * QKP + offB,         bhp + (it_) * 8);           \
        cpasync16(bl + rowB * QKP + offB,         blp + (it_) * 8);           \
    }

    QKV_ISSUE(0, 0);
    asm volatile("cp.async.commit_group;");

    for (int it = 0; it < nk; it++) {
        const int s = it & 1;
        if (it + 1 < nk) {
            QKV_ISSUE(s ^ 1, it + 1);
            asm volatile("cp.async.commit_group;");
            asm volatile("cp.async.wait_group 1;");
        } else {
            asm volatile("cp.async.wait_group 0;");
        }
        __syncthreads();

        const float*    Ab  = AsS + s * 128 * QALD;
        const uint32_t* Bhb = BhS + s * 128 * QKP;
        const uint32_t* Blb = BlS + s * 128 * QKP;

        uint32_t bhv[4][2], blv[4][2];
#pragma unroll
        for (int nt = 0; nt < 4; nt++) {
            int n = wn + nt * 8 + g;
            bhv[nt][0] = Bhb[n * QKP + tg];
            bhv[nt][1] = Bhb[n * QKP + tg + 4];
            blv[nt][0] = Blb[n * QKP + tg];
            blv[nt][1] = Blb[n * QKP + tg + 4];
        }
#pragma unroll
        for (int mt = 0; mt < 4; mt++) {
            int m = wm + mt * 16 + g;
            float2 q0 = *(const float2*)&Ab[m * QALD + 2 * tg];
            float2 q1 = *(const float2*)&Ab[(m + 8) * QALD + 2 * tg];
            float2 q2 = *(const float2*)&Ab[m * QALD + 2 * tg + 8];
            float2 q3 = *(const float2*)&Ab[(m + 8) * QALD + 2 * tg + 8];
            uint32_t ah[4], al[4];
            bfsplit2(q0.x, q0.y, ah[0], al[0]);
            bfsplit2(q1.x, q1.y, ah[1], al[1]);
            bfsplit2(q2.x, q2.y, ah[2], al[2]);
            bfsplit2(q3.x, q3.y, ah[3], al[3]);
#pragma unroll
            for (int nt = 0; nt < 4; nt++) {
                mma16(acc[mt][nt], ah[0], ah[1], ah[2], ah[3], bhv[nt][0], bhv[nt][1]);
                mma16(acc[mt][nt], ah[0], ah[1], ah[2], ah[3], blv[nt][0], blv[nt][1]);
                mma16(acc[mt][nt], al[0], al[1], al[2], al[3], bhv[nt][0], bhv[nt][1]);
            }
        }
        __syncthreads();
    }

#pragma unroll
    for (int mt = 0; mt < 4; mt++) {
        int row = bm + wm + mt * 16 + g;
#pragma unroll
        for (int nt = 0; nt < 4; nt++) {
            int col = bn + wn + nt * 8 + tg * 2;
            float b0 = bias[col], b1 = bias[col + 1];
            float2 v0 = make_float2(acc[mt][nt][0] + b0, acc[mt][nt][1] + b1);
            float2 v1 = make_float2(acc[mt][nt][2] + b0, acc[mt][nt][3] + b1);
            *(float2*)(C + (size_t)row * N + col) = v0;
            *(float2*)(C + (size_t)(row + 8) * N + col) = v1;
        }
    }
}

// ---------------------------------------------------------------------------
// Out-proj GEMM (v5, R7/R8-proven): both operands pre-split gmem planes.
// ---------------------------------------------------------------------------
#define GKP 20
#define G5PLANE (128 * GKP)
#define G5_SMEM_BYTES (2 * 4 * G5PLANE * 4)

__global__ __launch_bounds__(256, 2) void gemm_nt_tc5(
    const uint32_t* __restrict__ Ahg, const uint32_t* __restrict__ Alg,
    const uint32_t* __restrict__ Bhg, const uint32_t* __restrict__ Blg,
    const float* __restrict__ bias, float* __restrict__ C,
    int K, int N)
{
    extern __shared__ uint32_t gsm[];
    const int Kp = K >> 1;

    const int bm = blockIdx.y * 128, bn = blockIdx.x * 128;
    const int tid = threadIdx.x, lane = tid & 31, warp = tid >> 5;
    const int wm = (warp >> 2) * 64, wn = (warp & 3) * 32;
    const int g = lane >> 2, tg = lane & 3;

    const int lrow = tid >> 1, lhalf = (tid & 1) * 8;
    const size_t aoff = (size_t)(bm + lrow) * Kp + lhalf;
    const size_t boff = (size_t)(bn + lrow) * Kp + lhalf;
    const int sdst = lrow * GKP + lhalf;

    float acc[4][4][4];
#pragma unroll
    for (int mt = 0; mt < 4; mt++)
#pragma unroll
        for (int nt = 0; nt < 4; nt++)
#pragma unroll
            for (int r = 0; r < 4; r++) acc[mt][nt][r] = 0.f;

    const int nk = K / 32;

#define G5_ISSUE(stage, kp0)                                                \
    {                                                                       \
        uint32_t* s0 = gsm + (stage) * 4 * G5PLANE;                         \
        cpasync16(s0 + sdst,                 Ahg + aoff + (kp0));           \
        cpasync16(s0 + sdst + 4,             Ahg + aoff + (kp0) + 4);       \
        cpasync16(s0 + G5PLANE + sdst,       Alg + aoff + (kp0));           \
        cpasync16(s0 + G5PLANE + sdst + 4,   Alg + aoff + (kp0) + 4);       \
        cpasync16(s0 + 2*G5PLANE + sdst,     Bhg + boff + (kp0));           \
        cpasync16(s0 + 2*G5PLANE + sdst + 4, Bhg + boff + (kp0) + 4);       \
        cpasync16(s0 + 3*G5PLANE + sdst,     Blg + boff + (kp0));           \
        cpasync16(s0 + 3*G5PLANE + sdst + 4, Blg + boff + (kp0) + 4);       \
    }

    G5_ISSUE(0, 0);
    asm volatile("cp.async.commit_group;");

    for (int it = 0; it < nk; it++) {
        const int s = it & 1;
        if (it + 1 < nk) {
            G5_ISSUE(s ^ 1, (it + 1) * 16);
            asm volatile("cp.async.commit_group;");
            asm volatile("cp.async.wait_group 1;");
        } else {
            asm volatile("cp.async.wait_group 0;");
        }
        __syncthreads();

        const uint32_t* Ah = gsm + s * 4 * G5PLANE;
        const uint32_t* Al = Ah + G5PLANE;
        const uint32_t* Bh = Ah + 2 * G5PLANE;
        const uint32_t* Bl = Ah + 3 * G5PLANE;

#pragma unroll
        for (int ks = 0; ks < 2; ks++) {
            const int kb = ks * 8;
            uint32_t bhv[4][2], blv[4][2];
#pragma unroll
            for (int nt = 0; nt < 4; nt++) {
                int n = wn + nt * 8 + g;
                bhv[nt][0] = Bh[n * GKP + kb + tg];
                bhv[nt][1] = Bh[n * GKP + kb + tg + 4];
                blv[nt][0] = Bl[n * GKP + kb + tg];
                blv[nt][1] = Bl[n * GKP + kb + tg + 4];
            }
#pragma unroll
            for (int mt = 0; mt < 4; mt++) {
                int m = wm + mt * 16 + g;
                uint32_t ah[4], al[4];
                ah[0] = Ah[m * GKP + kb + tg];
                ah[1] = Ah[(m + 8) * GKP + kb + tg];
                ah[2] = Ah[m * GKP + kb + tg + 4];
                ah[3] = Ah[(m + 8) * GKP + kb + tg + 4];
                al[0] = Al[m * GKP + kb + tg];
                al[1] = Al[(m + 8) * GKP + kb + tg];
                al[2] = Al[m * GKP + kb + tg + 4];
                al[3] = Al[(m + 8) * GKP + kb + tg + 4];
#pragma unroll
                for (int nt = 0; nt < 4; nt++) {
                    mma16(acc[mt][nt], ah[0], ah[1], ah[2], ah[3], bhv[nt][0], bhv[nt][1]);
                    mma16(acc[mt][nt], ah[0], ah[1], ah[2], ah[3], blv[nt][0], blv[nt][1]);
                    mma16(acc[mt][nt], al[0], al[1], al[2], al[3], bhv[nt][0], bhv[nt][1]);
                }
            }
        }
        __syncthreads();
    }

#pragma unroll
    for (int mt = 0; mt < 4; mt++) {
        int row = bm + wm + mt * 16 + g;
#pragma unroll
        for (int nt = 0; nt < 4; nt++) {
            int col = bn + wn + nt * 8 + tg * 2;
            float b0 = bias[col], b1 = bias[col + 1];
            float2 v0 = make_float2(acc[mt][nt][0] + b0, acc[mt][nt][1] + b1);
            float2 v1 = make_float2(acc[mt][nt][2] + b0, acc[mt][nt][3] + b1);
            *(float2*)(C + (size_t)row * N + col) = v0;
            *(float2*)(C + (size_t)(row + 8) * N + col) = v1;
        }
    }
}

// ---------------------------------------------------------------------------
// Fused attention v2: P register-forwarded from S C-fragments into AV
// A-fragments (no Ph/Pl smem, no P barrier). V gather-loaded pre-transposed.
// smem (uint32 words): Qh@0[128][36], Ql@4608, Kh@9216[32][36], Kl@10368,
// Vh@11520[64][20], Vl@12800, rs@14080[128] -> 14208 words = 56832 B.
// 3 CTAs/SM (reg-capped at 85 by launch bounds).
// ---------------------------------------------------------------------------
#define IT 128
#define JT 32
#define FA_SMEM_BYTES 56832

__global__ __launch_bounds__(256, 3) void fused_attn(float* __restrict__ attn)
{
    extern __shared__ uint32_t smu[];
    uint32_t* Qh = smu;
    uint32_t* Ql = smu + 4608;
    uint32_t* Kh = smu + 9216;
    uint32_t* Kl = smu + 10368;
    uint32_t* Vh = smu + 11520;
    uint32_t* Vl = smu + 12800;
    float*    rs = (float*)(smu + 14080);

    const int bh = blockIdx.z, b = bh >> 4, h = bh & 15;
    const int itile = (gridDim.x - 1) - blockIdx.x;   // heavy tiles first
    const int i0 = itile * IT;
    const int tid = threadIdx.x, lane = tid & 31, warp = tid >> 5;
    const int g = lane >> 2, tg = lane & 3;
    const int wm = warp * 16;                         // warp rows (S and AV)

    // ---- load + split Q tile once ----
#pragma unroll
    for (int u = 0; u < 8; u++) {
        int idx = tid + u * 256;
        int row = idx >> 4, c4 = (idx & 15) * 4;
        float4 v = *(const float4*)(g_Qp + (size_t)(b * SS + i0 + row) * DD + h * DK + c4);
        uint32_t h0, l0, h1, l1;
        bfsplit2(v.x, v.y, h0, l0);
        bfsplit2(v.z, v.w, h1, l1);
        *(uint2*)&Qh[row * 36 + (c4 >> 1)] = make_uint2(h0, h1);
        *(uint2*)&Ql[row * 36 + (c4 >> 1)] = make_uint2(l0, l1);
    }

    float acc_v[8][4];
#pragma unroll
    for (int nt = 0; nt < 8; nt++)
#pragma unroll
        for (int r = 0; r < 4; r++) acc_v[nt][r] = 0.f;
    float rs0 = 0.f, rs1 = 0.f;

    // K loader: rows krow0/krow1, 4 cols each (float4)
    const int krow0 = tid >> 4, kc4 = (tid & 15) * 4;
    const int krow1 = krow0 + 16;
    // V loader (transposed gather): d = vn, jpairs vjp0 + 4e
    const int vn = tid & 63, vjp0 = tid >> 6;
    const float* vbase = g_Vp + (size_t)(b * SS) * DD + h * DK + vn;

    const int nj = (i0 >> 5) + 4;
    float4 kk0, kk1;
    float2 vv[4];
    kk0 = *(const float4*)(g_Kp + (size_t)(b * SS + krow0) * DD + h * DK + kc4);
    kk1 = *(const float4*)(g_Kp + (size_t)(b * SS + krow1) * DD + h * DK + kc4);
#pragma unroll
    for (int e = 0; e < 4; e++) {
        int j = 2 * (vjp0 + 4 * e);
        vv[e].x = vbase[(size_t)j * DD];
        vv[e].y = vbase[(size_t)(j + 1) * DD];
    }

    const int m0 = wm + g;
    const int gi0 = i0 + m0, gi1 = gi0 + 8;
    float* arow0 = attn + ((size_t)bh * SS + gi0) * SS;
    float* arow1 = attn + ((size_t)bh * SS + gi1) * SS;

    for (int t = 0; t < nj; t++) {
        const int j0 = t * JT;
        __syncthreads();   // prev chunk's Kh/Kl/Vh/Vl fully consumed
        {   // K split-store
            uint32_t h0, l0, h1, l1;
            bfsplit2(kk0.x, kk0.y, h0, l0);
            bfsplit2(kk0.z, kk0.w, h1, l1);
            *(uint2*)&Kh[krow0 * 36 + (kc4 >> 1)] = make_uint2(h0, h1);
            *(uint2*)&Kl[krow0 * 36 + (kc4 >> 1)] = make_uint2(l0, l1);
            bfsplit2(kk1.x, kk1.y, h0, l0);
            bfsplit2(kk1.z, kk1.w, h1, l1);
            *(uint2*)&Kh[krow1 * 36 + (kc4 >> 1)] = make_uint2(h0, h1);
            *(uint2*)&Kl[krow1 * 36 + (kc4 >> 1)] = make_uint2(l0, l1);
        }
        {   // V split-store (already transposed)
#pragma unroll
            for (int e = 0; e < 4; e++) {
                int jp = vjp0 + 4 * e;
                uint32_t hh, ll;
                bfsplit2(vv[e].x, vv[e].y, hh, ll);
                Vh[vn * 20 + jp] = hh;
                Vl[vn * 20 + jp] = ll;
            }
        }
        __syncthreads();   // K/V tiles ready
        if (t + 1 < nj) {
            const int j0n = j0 + JT;
            kk0 = *(const float4*)(g_Kp + (size_t)(b * SS + j0n + krow0) * DD + h * DK + kc4);
            kk1 = *(const float4*)(g_Kp + (size_t)(b * SS + j0n + krow1) * DD + h * DK + kc4);
#pragma unroll
            for (int e = 0; e < 4; e++) {
                int j = j0n + 2 * (vjp0 + 4 * e);
                vv[e].x = vbase[(size_t)j * DD];
                vv[e].y = vbase[(size_t)(j + 1) * DD];
            }
        }

        // ---- S = Q.K^T  (warp: 16 rows x 32 cols) ----
        float acc_s[4][4];
#pragma unroll
        for (int nt = 0; nt < 4; nt++)
#pragma unroll
            for (int r = 0; r < 4; r++) acc_s[nt][r] = 0.f;

#pragma unroll
        for (int s4 = 0; s4 < 4; s4++) {
            const int kb = s4 * 8;
            uint32_t ah[4], al[4];
            ah[0] = Qh[m0 * 36 + kb + tg];           al[0] = Ql[m0 * 36 + kb + tg];
            ah[1] = Qh[(m0 + 8) * 36 + kb + tg];     al[1] = Ql[(m0 + 8) * 36 + kb + tg];
            ah[2] = Qh[m0 * 36 + kb + tg + 4];       al[2] = Ql[m0 * 36 + kb + tg + 4];
            ah[3] = Qh[(m0 + 8) * 36 + kb + tg + 4]; al[3] = Ql[(m0 + 8) * 36 + kb + tg + 4];
#pragma unroll
            for (int nt = 0; nt < 4; nt++) {
                int n = nt * 8 + g;
                uint32_t bh0 = Kh[n * 36 + kb + tg];
                uint32_t bh1 = Kh[n * 36 + kb + tg + 4];
                uint32_t bl0 = Kl[n * 36 + kb + tg];
                uint32_t bl1 = Kl[n * 36 + kb + tg + 4];
                mma16(acc_s[nt], ah[0], ah[1], ah[2], ah[3], bh0, bh1);
                mma16(acc_s[nt], ah[0], ah[1], ah[2], ah[3], bl0, bl1);
                mma16(acc_s[nt], al[0], al[1], al[2], al[3], bh0, bh1);
            }
        }

        // ---- exp, mask, rowsum, write attn, build P A-fragments in regs ----
        uint32_t pah[2][4], pal[2][4];
        const bool needmask = (j0 + JT - 1 > gi0);
#pragma unroll
        for (int nt = 0; nt < 4; nt++) {
            int cl = nt * 8 + tg * 2;
            int c = j0 + cl;
            float p00 = __expf(acc_s[nt][0] * 0.125f);
            float p01 = __expf(acc_s[nt][1] * 0.125f);
            float p10 = __expf(acc_s[nt][2] * 0.125f);
            float p11 = __expf(acc_s[nt][3] * 0.125f);
            if (needmask) {
                if (c     > gi0) p00 = 0.f;
                if (c + 1 > gi0) p01 = 0.f;
                if (c     > gi1) p10 = 0.f;
                if (c + 1 > gi1) p11 = 0.f;
            }
            rs0 += p00 + p01;
            rs1 += p10 + p11;
            __stcs((float2*)(arow0 + c), make_float2(p00, p01));
            __stcs((float2*)(arow1 + c), make_float2(p10, p11));
            const int bb = nt >> 1;
            if ((nt & 1) == 0) {
                bfsplit2(p00, p01, pah[bb][0], pal[bb][0]);
                bfsplit2(p10, p11, pah[bb][1], pal[bb][1]);
            } else {
                bfsplit2(p00, p01, pah[bb][2], pal[bb][2]);
                bfsplit2(p10, p11, pah[bb][3], pal[bb][3]);
            }
        }

        // ---- X_acc += P @ V  (warp: its own 16 rows x 64 d, P in regs) ----
#pragma unroll
        for (int bb = 0; bb < 2; bb++) {
            const int kb = bb * 8;
#pragma unroll
            for (int nt = 0; nt < 8; nt++) {
                int n = nt * 8 + g;
                uint32_t vh0 = Vh[n * 20 + kb + tg];
                uint32_t vh1 = Vh[n * 20 + kb + tg + 4];
                uint32_t vl0 = Vl[n * 20 + kb + tg];
                uint32_t vl1 = Vl[n * 20 + kb + tg + 4];
                mma16(acc_v[nt], pah[bb][0], pah[bb][1], pah[bb][2], pah[bb][3], vh0, vh1);
                mma16(acc_v[nt], pah[bb][0], pah[bb][1], pah[bb][2], pah[bb][3], vl0, vl1);
                mma16(acc_v[nt], pal[bb][0], pal[bb][1], pal[bb][2], pal[bb][3], vh0, vh1);
            }
        }
    }

    // ---- rowsum reduce over tg lanes ----
    rs0 += __shfl_xor_sync(0xffffffffu, rs0, 1);
    rs0 += __shfl_xor_sync(0xffffffffu, rs0, 2);
    rs1 += __shfl_xor_sync(0xffffffffu, rs1, 1);
    rs1 += __shfl_xor_sync(0xffffffffu, rs1, 2);
    if (tg == 0) { rs[m0] = rs0; rs[m0 + 8] = rs1; }
    __syncthreads();
    if (tid < 128) g_rinv[(size_t)bh * SS + i0 + tid] = 1.0f / rs[tid];

    // ---- X = X_acc / rowsum, written directly as bf16x2 hi/lo planes ----
    {
        const int Kp2 = DD / 2;
        const float inv0 = 1.0f / rs0, inv1 = 1.0f / rs1;
        const size_t w0 = (size_t)(b * SS + i0 + m0) * Kp2 + h * (DK / 2);
        const size_t w1 = (size_t)(b * SS + i0 + m0 + 8) * Kp2 + h * (DK / 2);
#pragma unroll
        for (int nt = 0; nt < 8; nt++) {
            int cp = nt * 4 + tg;
            uint32_t hh, ll;
            bfsplit2(acc_v[nt][0] * inv0, acc_v[nt][1] * inv0, hh, ll);
            g_xh[w0 + cp] = hh; g_xl[w0 + cp] = ll;
            bfsplit2(acc_v[nt][2] * inv1, acc_v[nt][3] * inv1, hh, ll);
            g_xh[w1 + cp] = hh; g_xl[w1 + cp] = ll;
        }
    }

    // ---- zero-fill strictly-upper tiles (d_out is poisoned) ----
    const int jend = i0 + IT;
    const int zw4 = (SS - jend) >> 2;
    if (zw4 > 0) {
        float4 z = make_float4(0.f, 0.f, 0.f, 0.f);
        for (int r = warp; r < IT; r += 8) {
            float* rowp = attn + ((size_t)bh * SS + i0 + r) * SS + jend;
            for (int cq = lane; cq < zw4; cq += 32)
                __stcs((float4*)(rowp + cq * 4), z);
        }
    }
}

// ---------------------------------------------------------------------------
// Normalize attn rows: p[0..i] *= 1/rowsum. One block per row. Streaming.
// ---------------------------------------------------------------------------
__global__ __launch_bounds__(256) void normalize_attn(float* __restrict__ attn)
{
    const int row = blockIdx.x;
    const int i = row & (SS - 1);
    const float inv = g_rinv[row];
    float* p = attn + (size_t)row * SS;
    const int L = i + 1;
    const int n4 = L >> 2;
    for (int q = threadIdx.x; q < n4; q += 256) {
        float4 v = __ldcs(((const float4*)p) + q);
        v.x *= inv; v.y *= inv; v.z *= inv; v.w *= inv;
        __stcs(((float4*)p) + q, v);
    }
    for (int q = (n4 << 2) + threadIdx.x; q < L; q += 256) p[q] *= inv;
}

// ---------------------------------------------------------------------------
extern "C" void kernel_launch(void* const* d_in, const int* in_sizes, int n_in,
                              void* d_out, int out_size)
{
    const float* q    = (const float*)d_in[0];
    const float* k    = (const float*)d_in[1];
    const float* v    = (const float*)d_in[2];
    // d_in[3] = mask (tril) — causality applied analytically
    const float* wq_w = (const float*)d_in[4];
    const float* wq_b = (const float*)d_in[5];
    const float* wk_w = (const float*)d_in[6];
    const float* wk_b = (const float*)d_in[7];
    const float* wv_w = (const float*)d_in[8];
    const float* wv_b = (const float*)d_in[9];
    const float* wo_w = (const float*)d_in[10];
    const float* wo_b = (const float*)d_in[11];

    float* out  = (float*)d_out;
    float* attn = (float*)d_out + OUT0;

    float *qp, *kp, *vp;
    cudaGetSymbolAddress((void**)&qp, g_Qp);
    cudaGetSymbolAddress((void**)&kp, g_Kp);
    cudaGetSymbolAddress((void**)&vp, g_Vp);

    uint32_t *xh, *xl, *wqh, *wql, *wkh, *wkl, *wvh, *wvl, *woh, *wol;
    cudaGetSymbolAddress((void**)&xh, g_xh);   cudaGetSymbolAddress((void**)&xl, g_xl);
    cudaGetSymbolAddress((void**)&wqh, g_wqh); cudaGetSymbolAddress((void**)&wql, g_wql);
    cudaGetSymbolAddress((void**)&wkh, g_wkh); cudaGetSymbolAddress((void**)&wkl, g_wkl);
    cudaGetSymbolAddress((void**)&wvh, g_wvh); cudaGetSymbolAddress((void**)&wvl, g_wvl);
    cudaGetSymbolAddress((void**)&woh, g_woh); cudaGetSymbolAddress((void**)&wol, g_wol);

    static bool attr_set = false;
    if (!attr_set) {
        cudaFuncSetAttribute(fused_attn, cudaFuncAttributeMaxDynamicSharedMemorySize,
                             FA_SMEM_BYTES);
        cudaFuncSetAttribute(gemm_nt_tc5, cudaFuncAttributeMaxDynamicSharedMemorySize,
                             G5_SMEM_BYTES);
        cudaFuncSetAttribute(gemm_qkv, cudaFuncAttributeMaxDynamicSharedMemorySize,
                             QKV_SMEM_BYTES);
        attr_set = true;
    }

    const int wqd = DD * DD / 4;

    // weights prep
    split_pack<<<(wqd + 255) / 256, 256>>>(wq_w, wqh, wql, wqd);
    split_pack<<<(wqd + 255) / 256, 256>>>(wk_w, wkh, wkl, wqd);
    split_pack<<<(wqd + 255) / 256, 256>>>(wv_w, wvh, wvl, wqd);
    split_pack<<<(wqd + 255) / 256, 256>>>(wo_w, woh, wol, wqd);

    // QKV projections, one batched launch
    dim3 gqkv(DD / 128, MM / 128, 3);      // (8, 64, 3)
    gemm_qkv<<<gqkv, 256, QKV_SMEM_BYTES>>>(q, k, v, wq_b, wk_b, wv_b, qp, kp, vp);

    dim3 gfa(SS / IT, 1, BB * HH);         // (16, 1, 64)
    fused_attn<<<gfa, 256, FA_SMEM_BYTES>>>(attn);

    normalize_attn<<<BB * HH * SS, 256>>>(attn);

    dim3 gproj(DD / 128, MM / 128);        // (8, 64)
    gemm_nt_tc5<<<gproj, 256, G5_SMEM_BYTES>>>(xh, xl, woh, wol, wo_b, out, DD, DD);
}

// round 12
// speedup vs baseline: 1.0323x; 1.0323x over previous
#include <cuda_runtime.h>
#include <stdint.h>
#include <math.h>

// Problem constants
#define BB 4
#define SS 2048
#define DD 1024
#define HH 16
#define DK 64
#define MM (BB * SS)                  // 8192 rows for projections
#define OUT0 ((size_t)BB * SS * DD)   // offset of attn in d_out (elements)

// Scratch (device globals)
__device__ __align__(16) float g_Qp[MM * DD];
__device__ __align__(16) float g_Kp[MM * DD];
__device__ __align__(16) float g_Vp[MM * DD];
__device__ float g_rinv[(size_t)BB * HH * SS];

// Pre-split planes (bf16x2 hi/lo packed along k-pairs)
#define APW (MM * DD / 2)
#define WPW (DD * DD / 2)
__device__ __align__(16) uint32_t g_xh[APW], g_xl[APW];
__device__ __align__(16) uint32_t g_wqh[WPW], g_wql[WPW];
__device__ __align__(16) uint32_t g_wkh[WPW], g_wkl[WPW];
__device__ __align__(16) uint32_t g_wvh[WPW], g_wvl[WPW];
__device__ __align__(16) uint32_t g_woh[WPW], g_wol[WPW];

// ---------------------------------------------------------------------------
// bf16x3 helpers
// ---------------------------------------------------------------------------
__device__ __forceinline__ void bfsplit2(float x0, float x1,
                                         uint32_t& hi, uint32_t& lo) {
    asm("cvt.rn.bf16x2.f32 %0, %1, %2;" : "=r"(hi) : "f"(x1), "f"(x0));
    float h0 = __uint_as_float(hi << 16);
    float h1 = __uint_as_float(hi & 0xffff0000u);
    asm("cvt.rn.bf16x2.f32 %0, %1, %2;" : "=r"(lo) : "f"(x1 - h1), "f"(x0 - h0));
}
__device__ __forceinline__ void mma16(float* c,
                                      uint32_t a0, uint32_t a1, uint32_t a2, uint32_t a3,
                                      uint32_t b0, uint32_t b1) {
    asm volatile(
        "mma.sync.aligned.m16n8k16.row.col.f32.bf16.bf16.f32 "
        "{%0,%1,%2,%3}, {%4,%5,%6,%7}, {%8,%9}, {%0,%1,%2,%3};"
        : "+f"(c[0]), "+f"(c[1]), "+f"(c[2]), "+f"(c[3])
        : "r"(a0), "r"(a1), "r"(a2), "r"(a3), "r"(b0), "r"(b1));
}
__device__ __forceinline__ void cpasync16(void* smem, const void* gmem) {
    uint32_t sa = (uint32_t)__cvta_generic_to_shared(smem);
    asm volatile("cp.async.cg.shared.global [%0], [%1], 16;" :: "r"(sa), "l"(gmem));
}

// ---------------------------------------------------------------------------
// Prep: split all 4 weight matrices in one launch (grid.y selects matrix).
// ---------------------------------------------------------------------------
struct SplitArgs {
    const float* src[4];
    uint32_t* hp[4];
    uint32_t* lp[4];
};

__global__ __launch_bounds__(256) void split_pack_w(SplitArgs sa, int nquads)
{
    int q = blockIdx.x * 256 + threadIdx.x;
    if (q >= nquads) return;
    const int w = blockIdx.y;
    float4 v = ((const float4*)sa.src[w])[q];
    uint32_t h0, l0, h1, l1;
    bfsplit2(v.x, v.y, h0, l0);
    bfsplit2(v.z, v.w, h1, l1);
    ((uint2*)sa.hp[w])[q] = make_uint2(h0, h1);
    ((uint2*)sa.lp[w])[q] = make_uint2(l0, l1);
}

// ---------------------------------------------------------------------------
// QKV batched GEMM (bf16x3): z selects (A, W-planes, bias, C).  (R8-proven)
// ---------------------------------------------------------------------------
#define QALD 24
#define QKP 12
#define QKV_SMEM_BYTES 49152

__global__ __launch_bounds__(256, 2) void gemm_qkv(
    const float* __restrict__ Aq, const float* __restrict__ Ak,
    const float* __restrict__ Av,
    const float* __restrict__ bq, const float* __restrict__ bk,
    const float* __restrict__ bv,
    float* __restrict__ Cq, float* __restrict__ Ck, float* __restrict__ Cv)
{
    extern __shared__ uint32_t qsm[];
    float*    AsS = (float*)qsm;
    uint32_t* BhS = qsm + 2 * 128 * QALD;
    uint32_t* BlS = BhS + 2 * 128 * QKP;

    const int K = DD, N = DD, Kp = DD / 2;
    const float* A; const uint32_t* Wh; const uint32_t* Wl;
    const float* bias; float* C;
    if (blockIdx.z == 0)      { A = Aq; Wh = g_wqh; Wl = g_wql; bias = bq; C = Cq; }
    else if (blockIdx.z == 1) { A = Ak; Wh = g_wkh; Wl = g_wkl; bias = bk; C = Ck; }
    else                      { A = Av; Wh = g_wvh; Wl = g_wvl; bias = bv; C = Cv; }

    const int bm = blockIdx.y * 128, bn = blockIdx.x * 128;
    const int tid = threadIdx.x, lane = tid & 31, warp = tid >> 5;
    const int wm = (warp >> 2) * 64, wn = (warp & 3) * 32;
    const int g = lane >> 2, tg = lane & 3;

    const int lrowA = tid >> 2, kkA = (tid & 3) * 4;
    const float* a0p = A + (size_t)(bm + lrowA) * K + kkA;
    const float* a1p = A + (size_t)(bm + lrowA + 64) * K + kkA;
    const int rowB = tid >> 1, offB = (tid & 1) * 4;
    const uint32_t* bhp = Wh + (size_t)(bn + rowB) * Kp + offB;
    const uint32_t* blp = Wl + (size_t)(bn + rowB) * Kp + offB;

    float acc[4][4][4];
#pragma unroll
    for (int mt = 0; mt < 4; mt++)
#pragma unroll
        for (int nt = 0; nt < 4; nt++)
#pragma unroll
            for (int r = 0; r < 4; r++) acc[mt][nt][r] = 0.f;

    const int nk = K / 16;

#define QKV_ISSUE(stage, it_)                                                 \
    {                                                                         \
        float*    as = AsS + (stage) * 128 * QALD;                            \
        uint32_t* bh = BhS + (stage) * 128 * QKP;                             \
        uint32_t* bl = BlS + (stage) * 128 * QKP;                             \
        cpasync16(as + lrowA * QALD + kkA,        a0p + (it_) * 16);          \
        cpasync16(as + (lrowA + 64) * QALD + kkA, a1p + (it_) * 16);          \
        cpasync16(bh + rowB * QKP + offB,         bhp + (it_) * 8);           \
        cpasync16(bl + rowB * QKP + offB,         blp + (it_) * 8);           \
    }

    QKV_ISSUE(0, 0);
    asm volatile("cp.async.commit_group;");

    for (int it = 0; it < nk; it++) {
        const int s = it & 1;
        if (it + 1 < nk) {
            QKV_ISSUE(s ^ 1, it + 1);
            asm volatile("cp.async.commit_group;");
            asm volatile("cp.async.wait_group 1;");
        } else {
            asm volatile("cp.async.wait_group 0;");
        }
        __syncthreads();

        const float*    Ab  = AsS + s * 128 * QALD;
        const uint32_t* Bhb = BhS + s * 128 * QKP;
        const uint32_t* Blb = BlS + s * 128 * QKP;

        uint32_t bhv[4][2], blv[4][2];
#pragma unroll
        for (int nt = 0; nt < 4; nt++) {
            int n = wn + nt * 8 + g;
            bhv[nt][0] = Bhb[n * QKP + tg];
            bhv[nt][1] = Bhb[n * QKP + tg + 4];
            blv[nt][0] = Blb[n * QKP + tg];
            blv[nt][1] = Blb[n * QKP + tg + 4];
        }
#pragma unroll
        for (int mt = 0; mt < 4; mt++) {
            int m = wm + mt * 16 + g;
            float2 q0 = *(const float2*)&Ab[m * QALD + 2 * tg];
            float2 q1 = *(const float2*)&Ab[(m + 8) * QALD + 2 * tg];
            float2 q2 = *(const float2*)&Ab[m * QALD + 2 * tg + 8];
            float2 q3 = *(const float2*)&Ab[(m + 8) * QALD + 2 * tg + 8];
            uint32_t ah[4], al[4];
            bfsplit2(q0.x, q0.y, ah[0], al[0]);
            bfsplit2(q1.x, q1.y, ah[1], al[1]);
            bfsplit2(q2.x, q2.y, ah[2], al[2]);
            bfsplit2(q3.x, q3.y, ah[3], al[3]);
#pragma unroll
            for (int nt = 0; nt < 4; nt++) {
                mma16(acc[mt][nt], ah[0], ah[1], ah[2], ah[3], bhv[nt][0], bhv[nt][1]);
                mma16(acc[mt][nt], ah[0], ah[1], ah[2], ah[3], blv[nt][0], blv[nt][1]);
                mma16(acc[mt][nt], al[0], al[1], al[2], al[3], bhv[nt][0], bhv[nt][1]);
            }
        }
        __syncthreads();
    }

#pragma unroll
    for (int mt = 0; mt < 4; mt++) {
        int row = bm + wm + mt * 16 + g;
#pragma unroll
        for (int nt = 0; nt < 4; nt++) {
            int col = bn + wn + nt * 8 + tg * 2;
            float b0 = bias[col], b1 = bias[col + 1];
            float2 v0 = make_float2(acc[mt][nt][0] + b0, acc[mt][nt][1] + b1);
            float2 v1 = make_float2(acc[mt][nt][2] + b0, acc[mt][nt][3] + b1);
            *(float2*)(C + (size_t)row * N + col) = v0;
            *(float2*)(C + (size_t)(row + 8) * N + col) = v1;
        }
    }
}

// ---------------------------------------------------------------------------
// Out-proj GEMM (v5, R7/R8-proven): both operands pre-split gmem planes.
// ---------------------------------------------------------------------------
#define GKP 20
#define G5PLANE (128 * GKP)
#define G5_SMEM_BYTES (2 * 4 * G5PLANE * 4)

__global__ __launch_bounds__(256, 2) void gemm_nt_tc5(
    const uint32_t* __restrict__ Ahg, const uint32_t* __restrict__ Alg,
    const uint32_t* __restrict__ Bhg, const uint32_t* __restrict__ Blg,
    const float* __restrict__ bias, float* __restrict__ C,
    int K, int N)
{
    extern __shared__ uint32_t gsm[];
    const int Kp = K >> 1;

    const int bm = blockIdx.y * 128, bn = blockIdx.x * 128;
    const int tid = threadIdx.x, lane = tid & 31, warp = tid >> 5;
    const int wm = (warp >> 2) * 64, wn = (warp & 3) * 32;
    const int g = lane >> 2, tg = lane & 3;

    const int lrow = tid >> 1, lhalf = (tid & 1) * 8;
    const size_t aoff = (size_t)(bm + lrow) * Kp + lhalf;
    const size_t boff = (size_t)(bn + lrow) * Kp + lhalf;
    const int sdst = lrow * GKP + lhalf;

    float acc[4][4][4];
#pragma unroll
    for (int mt = 0; mt < 4; mt++)
#pragma unroll
        for (int nt = 0; nt < 4; nt++)
#pragma unroll
            for (int r = 0; r < 4; r++) acc[mt][nt][r] = 0.f;

    const int nk = K / 32;

#define G5_ISSUE(stage, kp0)                                                \
    {                                                                       \
        uint32_t* s0 = gsm + (stage) * 4 * G5PLANE;                         \
        cpasync16(s0 + sdst,                 Ahg + aoff + (kp0));           \
        cpasync16(s0 + sdst + 4,             Ahg + aoff + (kp0) + 4);       \
        cpasync16(s0 + G5PLANE + sdst,       Alg + aoff + (kp0));           \
        cpasync16(s0 + G5PLANE + sdst + 4,   Alg + aoff + (kp0) + 4);       \
        cpasync16(s0 + 2*G5PLANE + sdst,     Bhg + boff + (kp0));           \
        cpasync16(s0 + 2*G5PLANE + sdst + 4, Bhg + boff + (kp0) + 4);       \
        cpasync16(s0 + 3*G5PLANE + sdst,     Blg + boff + (kp0));           \
        cpasync16(s0 + 3*G5PLANE + sdst + 4, Blg + boff + (kp0) + 4);       \
    }

    G5_ISSUE(0, 0);
    asm volatile("cp.async.commit_group;");

    for (int it = 0; it < nk; it++) {
        const int s = it & 1;
        if (it + 1 < nk) {
            G5_ISSUE(s ^ 1, (it + 1) * 16);
            asm volatile("cp.async.commit_group;");
            asm volatile("cp.async.wait_group 1;");
        } else {
            asm volatile("cp.async.wait_group 0;");
        }
        __syncthreads();

        const uint32_t* Ah = gsm + s * 4 * G5PLANE;
        const uint32_t* Al = Ah + G5PLANE;
        const uint32_t* Bh = Ah + 2 * G5PLANE;
        const uint32_t* Bl = Ah + 3 * G5PLANE;

#pragma unroll
        for (int ks = 0; ks < 2; ks++) {
            const int kb = ks * 8;
            uint32_t bhv[4][2], blv[4][2];
#pragma unroll
            for (int nt = 0; nt < 4; nt++) {
                int n = wn + nt * 8 + g;
                bhv[nt][0] = Bh[n * GKP + kb + tg];
                bhv[nt][1] = Bh[n * GKP + kb + tg + 4];
                blv[nt][0] = Bl[n * GKP + kb + tg];
                blv[nt][1] = Bl[n * GKP + kb + tg + 4];
            }
#pragma unroll
            for (int mt = 0; mt < 4; mt++) {
                int m = wm + mt * 16 + g;
                uint32_t ah[4], al[4];
                ah[0] = Ah[m * GKP + kb + tg];
                ah[1] = Ah[(m + 8) * GKP + kb + tg];
                ah[2] = Ah[m * GKP + kb + tg + 4];
                ah[3] = Ah[(m + 8) * GKP + kb + tg + 4];
                al[0] = Al[m * GKP + kb + tg];
                al[1] = Al[(m + 8) * GKP + kb + tg];
                al[2] = Al[m * GKP + kb + tg + 4];
                al[3] = Al[(m + 8) * GKP + kb + tg + 4];
#pragma unroll
                for (int nt = 0; nt < 4; nt++) {
                    mma16(acc[mt][nt], ah[0], ah[1], ah[2], ah[3], bhv[nt][0], bhv[nt][1]);
                    mma16(acc[mt][nt], ah[0], ah[1], ah[2], ah[3], blv[nt][0], blv[nt][1]);
                    mma16(acc[mt][nt], al[0], al[1], al[2], al[3], bhv[nt][0], bhv[nt][1]);
                }
            }
        }
        __syncthreads();
    }

#pragma unroll
    for (int mt = 0; mt < 4; mt++) {
        int row = bm + wm + mt * 16 + g;
#pragma unroll
        for (int nt = 0; nt < 4; nt++) {
            int col = bn + wn + nt * 8 + tg * 2;
            float b0 = bias[col], b1 = bias[col + 1];
            float2 v0 = make_float2(acc[mt][nt][0] + b0, acc[mt][nt][1] + b1);
            float2 v1 = make_float2(acc[mt][nt][2] + b0, acc[mt][nt][3] + b1);
            *(float2*)(C + (size_t)row * N + col) = v0;
            *(float2*)(C + (size_t)(row + 8) * N + col) = v1;
        }
    }
}

// ---------------------------------------------------------------------------
// Fused attention (R8-proven core, only delta: .cs streaming attn stores):
// writes unnormalized P + 1/rowsum; X written directly as hi/lo planes;
// zero-fill of strictly-upper tiles at the tail.
// ---------------------------------------------------------------------------
#define IT 128
#define JT 32
#define FA_SMEM_BYTES 86016

__global__ __launch_bounds__(256) void fused_attn(float* __restrict__ attn)
{
    extern __shared__ uint32_t smu[];
    uint32_t* Qh = smu;
    uint32_t* Ql = smu + 4608;
    uint32_t* Kh = smu + 9216;
    uint32_t* Kl = smu + 10368;
    float*    Vs = (float*)(smu + 11520);
    uint32_t* Vh = smu + 13696;
    uint32_t* Vl = smu + 14976;
    uint32_t* Ph = smu + 16256;
    uint32_t* Pl = smu + 18816;
    float*    rs = (float*)(smu + 21376);

    const int bh = blockIdx.z, b = bh >> 4, h = bh & 15;
    const int itile = (gridDim.x - 1) - blockIdx.x;
    const int i0 = itile * IT;
    const int tid = threadIdx.x, lane = tid & 31, warp = tid >> 5;
    const int g = lane >> 2, tg = lane & 3;
    const int wm = warp * 16;
    const int wmv = (warp >> 1) * 32, wnv = (warp & 1) * 32;

#pragma unroll
    for (int u = 0; u < 8; u++) {
        int idx = tid + u * 256;
        int row = idx >> 4, c4 = (idx & 15) * 4;
        float4 v = *(const float4*)(g_Qp + (size_t)(b * SS + i0 + row) * DD + h * DK + c4);
        uint32_t h0, l0, h1, l1;
        bfsplit2(v.x, v.y, h0, l0);
        bfsplit2(v.z, v.w, h1, l1);
        *(uint2*)&Qh[row * 36 + (c4 >> 1)] = make_uint2(h0, h1);
        *(uint2*)&Ql[row * 36 + (c4 >> 1)] = make_uint2(l0, l1);
    }

    float acc_v[2][4][4];
#pragma unroll
    for (int mt = 0; mt < 2; mt++)
#pragma unroll
        for (int nt = 0; nt < 4; nt++)
#pragma unroll
            for (int r = 0; r < 4; r++) acc_v[mt][nt][r] = 0.f;
    float rs0 = 0.f, rs1 = 0.f;

    const int krow0 = tid >> 4, kc4 = (tid & 15) * 4;
    const int krow1 = krow0 + 16;

    const int nj = (i0 >> 5) + 4;
    float4 kv[4];
    kv[0] = *(const float4*)(g_Kp + (size_t)(b * SS + krow0) * DD + h * DK + kc4);
    kv[1] = *(const float4*)(g_Kp + (size_t)(b * SS + krow1) * DD + h * DK + kc4);
    kv[2] = *(const float4*)(g_Vp + (size_t)(b * SS + krow0) * DD + h * DK + kc4);
    kv[3] = *(const float4*)(g_Vp + (size_t)(b * SS + krow1) * DD + h * DK + kc4);

    const int m0 = wm + g;
    const int gi0 = i0 + m0, gi1 = gi0 + 8;
    float* arow0 = attn + ((size_t)bh * SS + gi0) * SS;
    float* arow1 = attn + ((size_t)bh * SS + gi1) * SS;

    for (int t = 0; t < nj; t++) {
        const int j0 = t * JT;
        __syncthreads();
        {
            uint32_t h0, l0, h1, l1;
            bfsplit2(kv[0].x, kv[0].y, h0, l0);
            bfsplit2(kv[0].z, kv[0].w, h1, l1);
            *(uint2*)&Kh[krow0 * 36 + (kc4 >> 1)] = make_uint2(h0, h1);
            *(uint2*)&Kl[krow0 * 36 + (kc4 >> 1)] = make_uint2(l0, l1);
            bfsplit2(kv[1].x, kv[1].y, h0, l0);
            bfsplit2(kv[1].z, kv[1].w, h1, l1);
            *(uint2*)&Kh[krow1 * 36 + (kc4 >> 1)] = make_uint2(h0, h1);
            *(uint2*)&Kl[krow1 * 36 + (kc4 >> 1)] = make_uint2(l0, l1);
            *(float4*)&Vs[krow0 * 68 + kc4] = kv[2];
            *(float4*)&Vs[krow1 * 68 + kc4] = kv[3];
        }
        __syncthreads();
        if (t + 1 < nj) {
            const int j0n = j0 + JT;
            kv[0] = *(const float4*)(g_Kp + (size_t)(b * SS + j0n + krow0) * DD + h * DK + kc4);
            kv[1] = *(const float4*)(g_Kp + (size_t)(b * SS + j0n + krow1) * DD + h * DK + kc4);
            kv[2] = *(const float4*)(g_Vp + (size_t)(b * SS + j0n + krow0) * DD + h * DK + kc4);
            kv[3] = *(const float4*)(g_Vp + (size_t)(b * SS + j0n + krow1) * DD + h * DK + kc4);
        }

        {
            int n = tid >> 2;
            int jp0 = tid & 3;
#pragma unroll
            for (int e = 0; e < 4; e++) {
                int jp = jp0 + e * 4;
                float v0 = Vs[(2 * jp) * 68 + n];
                float v1 = Vs[(2 * jp + 1) * 68 + n];
                uint32_t hh, ll;
                bfsplit2(v0, v1, hh, ll);
                Vh[n * 20 + jp] = hh;
                Vl[n * 20 + jp] = ll;
            }
        }

        float acc_s[4][4];
#pragma unroll
        for (int nt = 0; nt < 4; nt++)
#pragma unroll
            for (int r = 0; r < 4; r++) acc_s[nt][r] = 0.f;

#pragma unroll
        for (int s4 = 0; s4 < 4; s4++) {
            const int kb = s4 * 8;
            uint32_t ah[4], al[4];
            ah[0] = Qh[m0 * 36 + kb + tg];           al[0] = Ql[m0 * 36 + kb + tg];
            ah[1] = Qh[(m0 + 8) * 36 + kb + tg];     al[1] = Ql[(m0 + 8) * 36 + kb + tg];
            ah[2] = Qh[m0 * 36 + kb + tg + 4];       al[2] = Ql[m0 * 36 + kb + tg + 4];
            ah[3] = Qh[(m0 + 8) * 36 + kb + tg + 4]; al[3] = Ql[(m0 + 8) * 36 + kb + tg + 4];
#pragma unroll
            for (int nt = 0; nt < 4; nt++) {
                int n = nt * 8 + g;
                uint32_t bh0 = Kh[n * 36 + kb + tg];
                uint32_t bh1 = Kh[n * 36 + kb + tg + 4];
                uint32_t bl0 = Kl[n * 36 + kb + tg];
                uint32_t bl1 = Kl[n * 36 + kb + tg + 4];
                mma16(acc_s[nt], ah[0], ah[1], ah[2], ah[3], bh0, bh1);
                mma16(acc_s[nt], ah[0], ah[1], ah[2], ah[3], bl0, bl1);
                mma16(acc_s[nt], al[0], al[1], al[2], al[3], bh0, bh1);
            }
        }

        const bool needmask = (j0 + JT - 1 > gi0);
#pragma unroll
        for (int nt = 0; nt < 4; nt++) {
            int cl = nt * 8 + tg * 2;
            int c = j0 + cl;
            float p00 = __expf(acc_s[nt][0] * 0.125f);
            float p01 = __expf(acc_s[nt][1] * 0.125f);
            float p10 = __expf(acc_s[nt][2] * 0.125f);
            float p11 = __expf(acc_s[nt][3] * 0.125f);
            if (needmask) {
                if (c     > gi0) p00 = 0.f;
                if (c + 1 > gi0) p01 = 0.f;
                if (c     > gi1) p10 = 0.f;
                if (c + 1 > gi1) p11 = 0.f;
            }
            rs0 += p00 + p01;
            rs1 += p10 + p11;
            __stcs((float2*)(arow0 + c), make_float2(p00, p01));
            __stcs((float2*)(arow1 + c), make_float2(p10, p11));
            uint32_t hh, ll;
            bfsplit2(p00, p01, hh, ll);
            Ph[m0 * 20 + nt * 4 + tg] = hh;
            Pl[m0 * 20 + nt * 4 + tg] = ll;
            bfsplit2(p10, p11, hh, ll);
            Ph[(m0 + 8) * 20 + nt * 4 + tg] = hh;
            Pl[(m0 + 8) * 20 + nt * 4 + tg] = ll;
        }
        __syncthreads();

#pragma unroll
        for (int s2 = 0; s2 < 2; s2++) {
            const int kb = s2 * 8;
            uint32_t pah[2][4], pal[2][4];
#pragma unroll
            for (int mt = 0; mt < 2; mt++) {
                int m = wmv + mt * 16 + g;
                pah[mt][0] = Ph[m * 20 + kb + tg];
                pah[mt][1] = Ph[(m + 8) * 20 + kb + tg];
                pah[mt][2] = Ph[m * 20 + kb + tg + 4];
                pah[mt][3] = Ph[(m + 8) * 20 + kb + tg + 4];
                pal[mt][0] = Pl[m * 20 + kb + tg];
                pal[mt][1] = Pl[(m + 8) * 20 + kb + tg];
                pal[mt][2] = Pl[m * 20 + kb + tg + 4];
                pal[mt][3] = Pl[(m + 8) * 20 + kb + tg + 4];
            }
#pragma unroll
            for (int nt = 0; nt < 4; nt++) {
                int n = wnv + nt * 8 + g;
                uint32_t vh0 = Vh[n * 20 + kb + tg];
                uint32_t vh1 = Vh[n * 20 + kb + tg + 4];
                uint32_t vl0 = Vl[n * 20 + kb + tg];
                uint32_t vl1 = Vl[n * 20 + kb + tg + 4];
#pragma unroll
                for (int mt = 0; mt < 2; mt++) {
                    mma16(acc_v[mt][nt], pah[mt][0], pah[mt][1], pah[mt][2], pah[mt][3], vh0, vh1);
                    mma16(acc_v[mt][nt], pah[mt][0], pah[mt][1], pah[mt][2], pah[mt][3], vl0, vl1);
                    mma16(acc_v[mt][nt], pal[mt][0], pal[mt][1], pal[mt][2], pal[mt][3], vh0, vh1);
                }
            }
        }
    }

    rs0 += __shfl_xor_sync(0xffffffffu, rs0, 1);
    rs0 += __shfl_xor_sync(0xffffffffu, rs0, 2);
    rs1 += __shfl_xor_sync(0xffffffffu, rs1, 1);
    rs1 += __shfl_xor_sync(0xffffffffu, rs1, 2);
    if (tg == 0) { rs[m0] = rs0; rs[m0 + 8] = rs1; }
    __syncthreads();
    if (tid < 128) g_rinv[(size_t)bh * SS + i0 + tid] = 1.0f / rs[tid];

    const int Kp2 = DD / 2;
#pragma unroll
    for (int mt = 0; mt < 2; mt++) {
        int r0 = wmv + mt * 16 + g, r1 = r0 + 8;
        float inv0 = 1.0f / rs[r0], inv1 = 1.0f / rs[r1];
        size_t w0 = (size_t)(b * SS + i0 + r0) * Kp2 + (h * DK + wnv) / 2;
        size_t w1 = (size_t)(b * SS + i0 + r1) * Kp2 + (h * DK + wnv) / 2;
#pragma unroll
        for (int nt = 0; nt < 4; nt++) {
            int cp = nt * 4 + tg;
            uint32_t hh, ll;
            bfsplit2(acc_v[mt][nt][0] * inv0, acc_v[mt][nt][1] * inv0, hh, ll);
            g_xh[w0 + cp] = hh; g_xl[w0 + cp] = ll;
            bfsplit2(acc_v[mt][nt][2] * inv1, acc_v[mt][nt][3] * inv1, hh, ll);
            g_xh[w1 + cp] = hh; g_xl[w1 + cp] = ll;
        }
    }

    const int jend = i0 + IT;
    const int zw4 = (SS - jend) >> 2;
    if (zw4 > 0) {
        float4 z = make_float4(0.f, 0.f, 0.f, 0.f);
        for (int r = warp; r < IT; r += 8) {
            float* rowp = attn + ((size_t)bh * SS + i0 + r) * SS + jend;
            for (int cq = lane; cq < zw4; cq += 32)
                __stcs((float4*)(rowp + cq * 4), z);
        }
    }
}

// ---------------------------------------------------------------------------
// Normalize attn rows: p[0..i] *= 1/rowsum. One block per row. Streaming.
// ---------------------------------------------------------------------------
__global__ __launch_bounds__(256) void normalize_attn(float* __restrict__ attn)
{
    const int row = blockIdx.x;
    const int i = row & (SS - 1);
    const float inv = g_rinv[row];
    float* p = attn + (size_t)row * SS;
    const int L = i + 1;
    const int n4 = L >> 2;
    for (int q = threadIdx.x; q < n4; q += 256) {
        float4 v = __ldcs(((const float4*)p) + q);
        v.x *= inv; v.y *= inv; v.z *= inv; v.w *= inv;
        __stcs(((float4*)p) + q, v);
    }
    for (int q = (n4 << 2) + threadIdx.x; q < L; q += 256) p[q] *= inv;
}

// ---------------------------------------------------------------------------
extern "C" void kernel_launch(void* const* d_in, const int* in_sizes, int n_in,
                              void* d_out, int out_size)
{
    const float* q    = (const float*)d_in[0];
    const float* k    = (const float*)d_in[1];
    const float* v    = (const float*)d_in[2];
    // d_in[3] = mask (tril) — causality applied analytically
    const float* wq_w = (const float*)d_in[4];
    const float* wq_b = (const float*)d_in[5];
    const float* wk_w = (const float*)d_in[6];
    const float* wk_b = (const float*)d_in[7];
    const float* wv_w = (const float*)d_in[8];
    const float* wv_b = (const float*)d_in[9];
    const float* wo_w = (const float*)d_in[10];
    const float* wo_b = (const float*)d_in[11];

    float* out  = (float*)d_out;
    float* attn = (float*)d_out + OUT0;

    float *qp, *kp, *vp;
    cudaGetSymbolAddress((void**)&qp, g_Qp);
    cudaGetSymbolAddress((void**)&kp, g_Kp);
    cudaGetSymbolAddress((void**)&vp, g_Vp);

    uint32_t *xh, *xl, *wqh, *wql, *wkh, *wkl, *wvh, *wvl, *woh, *wol;
    cudaGetSymbolAddress((void**)&xh, g_xh);   cudaGetSymbolAddress((void**)&xl, g_xl);
    cudaGetSymbolAddress((void**)&wqh, g_wqh); cudaGetSymbolAddress((void**)&wql, g_wql);
    cudaGetSymbolAddress((void**)&wkh, g_wkh); cudaGetSymbolAddress((void**)&wkl, g_wkl);
    cudaGetSymbolAddress((void**)&wvh, g_wvh); cudaGetSymbolAddress((void**)&wvl, g_wvl);
    cudaGetSymbolAddress((void**)&woh, g_woh); cudaGetSymbolAddress((void**)&wol, g_wol);

    static bool attr_set = false;
    if (!attr_set) {
        cudaFuncSetAttribute(fused_attn, cudaFuncAttributeMaxDynamicSharedMemorySize,
                             FA_SMEM_BYTES);
        cudaFuncSetAttribute(gemm_nt_tc5, cudaFuncAttributeMaxDynamicSharedMemorySize,
                             G5_SMEM_BYTES);
        cudaFuncSetAttribute(gemm_qkv, cudaFuncAttributeMaxDynamicSharedMemorySize,
                             QKV_SMEM_BYTES);
        attr_set = true;
    }

    const int wqd = DD * DD / 4;

    // weights prep: all 4 matrices in one launch
    SplitArgs sa;
    sa.src[0] = wq_w; sa.hp[0] = wqh; sa.lp[0] = wql;
    sa.src[1] = wk_w; sa.hp[1] = wkh; sa.lp[1] = wkl;
    sa.src[2] = wv_w; sa.hp[2] = wvh; sa.lp[2] = wvl;
    sa.src[3] = wo_w; sa.hp[3] = woh; sa.lp[3] = wol;
    dim3 gsp((wqd + 255) / 256, 4);
    split_pack_w<<<gsp, 256>>>(sa, wqd);

    // QKV projections, one batched launch
    dim3 gqkv(DD / 128, MM / 128, 3);      // (8, 64, 3)
    gemm_qkv<<<gqkv, 256, QKV_SMEM_BYTES>>>(q, k, v, wq_b, wk_b, wv_b, qp, kp, vp);

    dim3 gfa(SS / IT, 1, BB * HH);         // (16, 1, 64)
    fused_attn<<<gfa, 256, FA_SMEM_BYTES>>>(attn);

    normalize_attn<<<BB * HH * SS, 256>>>(attn);

    dim3 gproj(DD / 128, MM / 128);        // (8, 64)
    gemm_nt_tc5<<<gproj, 256, G5_SMEM_BYTES>>>(xh, xl, woh, wol, wo_b, out, DD, DD);
}

// round 13
// speedup vs baseline: 1.0549x; 1.0219x over previous
#include <cuda_runtime.h>
#include <stdint.h>
#include <math.h>

// Problem constants
#define BB 4
#define SS 2048
#define DD 1024
#define HH 16
#define DK 64
#define MM (BB * SS)                  // 8192 rows for projections
#define OUT0 ((size_t)BB * SS * DD)   // offset of attn in d_out (elements)

// Scratch (device globals)
__device__ __align__(16) float g_Qp[MM * DD];
__device__ __align__(16) float g_Kp[MM * DD];
__device__ __align__(16) float g_Vp[MM * DD];
__device__ float g_rinv[(size_t)BB * HH * SS];

// Pre-split planes (bf16x2 hi/lo packed along k-pairs)
#define APW (MM * DD / 2)
#define WPW (DD * DD / 2)
__device__ __align__(16) uint32_t g_xh[APW], g_xl[APW];
__device__ __align__(16) uint32_t g_wqh[WPW], g_wql[WPW];
__device__ __align__(16) uint32_t g_wkh[WPW], g_wkl[WPW];
__device__ __align__(16) uint32_t g_wvh[WPW], g_wvl[WPW];
__device__ __align__(16) uint32_t g_woh[WPW], g_wol[WPW];

// ---------------------------------------------------------------------------
// bf16x3 helpers
// ---------------------------------------------------------------------------
__device__ __forceinline__ void bfsplit2(float x0, float x1,
                                         uint32_t& hi, uint32_t& lo) {
    asm("cvt.rn.bf16x2.f32 %0, %1, %2;" : "=r"(hi) : "f"(x1), "f"(x0));
    float h0 = __uint_as_float(hi << 16);
    float h1 = __uint_as_float(hi & 0xffff0000u);
    asm("cvt.rn.bf16x2.f32 %0, %1, %2;" : "=r"(lo) : "f"(x1 - h1), "f"(x0 - h0));
}
__device__ __forceinline__ void mma16(float* c,
                                      uint32_t a0, uint32_t a1, uint32_t a2, uint32_t a3,
                                      uint32_t b0, uint32_t b1) {
    asm volatile(
        "mma.sync.aligned.m16n8k16.row.col.f32.bf16.bf16.f32 "
        "{%0,%1,%2,%3}, {%4,%5,%6,%7}, {%8,%9}, {%0,%1,%2,%3};"
        : "+f"(c[0]), "+f"(c[1]), "+f"(c[2]), "+f"(c[3])
        : "r"(a0), "r"(a1), "r"(a2), "r"(a3), "r"(b0), "r"(b1));
}
__device__ __forceinline__ void cpasync16(void* smem, const void* gmem) {
    uint32_t sa = (uint32_t)__cvta_generic_to_shared(smem);
    asm volatile("cp.async.cg.shared.global [%0], [%1], 16;" :: "r"(sa), "l"(gmem));
}

// ---------------------------------------------------------------------------
// Prep: split all 4 weight matrices in one launch (grid.y selects matrix).
// ---------------------------------------------------------------------------
struct SplitArgs {
    const float* src[4];
    uint32_t* hp[4];
    uint32_t* lp[4];
};

__global__ __launch_bounds__(256) void split_pack_w(SplitArgs sa, int nquads)
{
    int q = blockIdx.x * 256 + threadIdx.x;
    if (q >= nquads) return;
    const int w = blockIdx.y;
    float4 v = ((const float4*)sa.src[w])[q];
    uint32_t h0, l0, h1, l1;
    bfsplit2(v.x, v.y, h0, l0);
    bfsplit2(v.z, v.w, h1, l1);
    ((uint2*)sa.hp[w])[q] = make_uint2(h0, h1);
    ((uint2*)sa.lp[w])[q] = make_uint2(l0, l1);
}

// ---------------------------------------------------------------------------
// QKV batched GEMM (bf16x3): z selects (A, W-planes, bias, C).  (R8-proven)
// ---------------------------------------------------------------------------
#define QALD 24
#define QKP 12
#define QKV_SMEM_BYTES 49152

__global__ __launch_bounds__(256, 2) void gemm_qkv(
    const float* __restrict__ Aq, const float* __restrict__ Ak,
    const float* __restrict__ Av,
    const float* __restrict__ bq, const float* __restrict__ bk,
    const float* __restrict__ bv,
    float* __restrict__ Cq, float* __restrict__ Ck, float* __restrict__ Cv)
{
    extern __shared__ uint32_t qsm[];
    float*    AsS = (float*)qsm;
    uint32_t* BhS = qsm + 2 * 128 * QALD;
    uint32_t* BlS = BhS + 2 * 128 * QKP;

    const int K = DD, N = DD, Kp = DD / 2;
    const float* A; const uint32_t* Wh; const uint32_t* Wl;
    const float* bias; float* C;
    if (blockIdx.z == 0)      { A = Aq; Wh = g_wqh; Wl = g_wql; bias = bq; C = Cq; }
    else if (blockIdx.z == 1) { A = Ak; Wh = g_wkh; Wl = g_wkl; bias = bk; C = Ck; }
    else                      { A = Av; Wh = g_wvh; Wl = g_wvl; bias = bv; C = Cv; }

    const int bm = blockIdx.y * 128, bn = blockIdx.x * 128;
    const int tid = threadIdx.x, lane = tid & 31, warp = tid >> 5;
    const int wm = (warp >> 2) * 64, wn = (warp & 3) * 32;
    const int g = lane >> 2, tg = lane & 3;

    const int lrowA = tid >> 2, kkA = (tid & 3) * 4;
    const float* a0p = A + (size_t)(bm + lrowA) * K + kkA;
    const float* a1p = A + (size_t)(bm + lrowA + 64) * K + kkA;
    const int rowB = tid >> 1, offB = (tid & 1) * 4;
    const uint32_t* bhp = Wh + (size_t)(bn + rowB) * Kp + offB;
    const uint32_t* blp = Wl + (size_t)(bn + rowB) * Kp + offB;

    float acc[4][4][4];
#pragma unroll
    for (int mt = 0; mt < 4; mt++)
#pragma unroll
        for (int nt = 0; nt < 4; nt++)
#pragma unroll
            for (int r = 0; r < 4; r++) acc[mt][nt][r] = 0.f;

    const int nk = K / 16;

#define QKV_ISSUE(stage, it_)                                                 \
    {                                                                         \
        float*    as = AsS + (stage) * 128 * QALD;                            \
        uint32_t* bh = BhS + (stage) * 128 * QKP;                             \
        uint32_t* bl = BlS + (stage) * 128 * QKP;                             \
        cpasync16(as + lrowA * QALD + kkA,        a0p + (it_) * 16);          \
        cpasync16(as + (lrowA + 64) * QALD + kkA, a1p + (it_) * 16);          \
        cpasync16(bh + rowB * QKP + offB,         bhp + (it_) * 8);           \
        cpasync16(bl + rowB * QKP + offB,         blp + (it_) * 8);           \
    }

    QKV_ISSUE(0, 0);
    asm volatile("cp.async.commit_group;");

    for (int it = 0; it < nk; it++) {
        const int s = it & 1;
        if (it + 1 < nk) {
            QKV_ISSUE(s ^ 1, it + 1);
            asm volatile("cp.async.commit_group;");
            asm volatile("cp.async.wait_group 1;");
        } else {
            asm volatile("cp.async.wait_group 0;");
        }
        __syncthreads();

        const float*    Ab  = AsS + s * 128 * QALD;
        const uint32_t* Bhb = BhS + s * 128 * QKP;
        const uint32_t* Blb = BlS + s * 128 * QKP;

        uint32_t bhv[4][2], blv[4][2];
#pragma unroll
        for (int nt = 0; nt < 4; nt++) {
            int n = wn + nt * 8 + g;
            bhv[nt][0] = Bhb[n * QKP + tg];
            bhv[nt][1] = Bhb[n * QKP + tg + 4];
            blv[nt][0] = Blb[n * QKP + tg];
            blv[nt][1] = Blb[n * QKP + tg + 4];
        }
#pragma unroll
        for (int mt = 0; mt < 4; mt++) {
            int m = wm + mt * 16 + g;
            float2 q0 = *(const float2*)&Ab[m * QALD + 2 * tg];
            float2 q1 = *(const float2*)&Ab[(m + 8) * QALD + 2 * tg];
            float2 q2 = *(const float2*)&Ab[m * QALD + 2 * tg + 8];
            float2 q3 = *(const float2*)&Ab[(m + 8) * QALD + 2 * tg + 8];
            uint32_t ah[4], al[4];
            bfsplit2(q0.x, q0.y, ah[0], al[0]);
            bfsplit2(q1.x, q1.y, ah[1], al[1]);
            bfsplit2(q2.x, q2.y, ah[2], al[2]);
            bfsplit2(q3.x, q3.y, ah[3], al[3]);
#pragma unroll
            for (int nt = 0; nt < 4; nt++) {
                mma16(acc[mt][nt], ah[0], ah[1], ah[2], ah[3], bhv[nt][0], bhv[nt][1]);
                mma16(acc[mt][nt], ah[0], ah[1], ah[2], ah[3], blv[nt][0], blv[nt][1]);
                mma16(acc[mt][nt], al[0], al[1], al[2], al[3], bhv[nt][0], bhv[nt][1]);
            }
        }
        __syncthreads();
    }

#pragma unroll
    for (int mt = 0; mt < 4; mt++) {
        int row = bm + wm + mt * 16 + g;
#pragma unroll
        for (int nt = 0; nt < 4; nt++) {
            int col = bn + wn + nt * 8 + tg * 2;
            float b0 = bias[col], b1 = bias[col + 1];
            float2 v0 = make_float2(acc[mt][nt][0] + b0, acc[mt][nt][1] + b1);
            float2 v1 = make_float2(acc[mt][nt][2] + b0, acc[mt][nt][3] + b1);
            *(float2*)(C + (size_t)row * N + col) = v0;
            *(float2*)(C + (size_t)(row + 8) * N + col) = v1;
        }
    }
}

// ---------------------------------------------------------------------------
// Out-proj GEMM (v5, R7/R8-proven): both operands pre-split gmem planes.
// ---------------------------------------------------------------------------
#define GKP 20
#define G5PLANE (128 * GKP)
#define G5_SMEM_BYTES (2 * 4 * G5PLANE * 4)

__global__ __launch_bounds__(256, 2) void gemm_nt_tc5(
    const uint32_t* __restrict__ Ahg, const uint32_t* __restrict__ Alg,
    const uint32_t* __restrict__ Bhg, const uint32_t* __restrict__ Blg,
    const float* __restrict__ bias, float* __restrict__ C,
    int K, int N)
{
    extern __shared__ uint32_t gsm[];
    const int Kp = K >> 1;

    const int bm = blockIdx.y * 128, bn = blockIdx.x * 128;
    const int tid = threadIdx.x, lane = tid & 31, warp = tid >> 5;
    const int wm = (warp >> 2) * 64, wn = (warp & 3) * 32;
    const int g = lane >> 2, tg = lane & 3;

    const int lrow = tid >> 1, lhalf = (tid & 1) * 8;
    const size_t aoff = (size_t)(bm + lrow) * Kp + lhalf;
    const size_t boff = (size_t)(bn + lrow) * Kp + lhalf;
    const int sdst = lrow * GKP + lhalf;

    float acc[4][4][4];
#pragma unroll
    for (int mt = 0; mt < 4; mt++)
#pragma unroll
        for (int nt = 0; nt < 4; nt++)
#pragma unroll
            for (int r = 0; r < 4; r++) acc[mt][nt][r] = 0.f;

    const int nk = K / 32;

#define G5_ISSUE(stage, kp0)                                                \
    {                                                                       \
        uint32_t* s0 = gsm + (stage) * 4 * G5PLANE;                         \
        cpasync16(s0 + sdst,                 Ahg + aoff + (kp0));           \
        cpasync16(s0 + sdst + 4,             Ahg + aoff + (kp0) + 4);       \
        cpasync16(s0 + G5PLANE + sdst,       Alg + aoff + (kp0));           \
        cpasync16(s0 + G5PLANE + sdst + 4,   Alg + aoff + (kp0) + 4);       \
        cpasync16(s0 + 2*G5PLANE + sdst,     Bhg + boff + (kp0));           \
        cpasync16(s0 + 2*G5PLANE + sdst + 4, Bhg + boff + (kp0) + 4);       \
        cpasync16(s0 + 3*G5PLANE + sdst,     Blg + boff + (kp0));           \
        cpasync16(s0 + 3*G5PLANE + sdst + 4, Blg + boff + (kp0) + 4);       \
    }

    G5_ISSUE(0, 0);
    asm volatile("cp.async.commit_group;");

    for (int it = 0; it < nk; it++) {
        const int s = it & 1;
        if (it + 1 < nk) {
            G5_ISSUE(s ^ 1, (it + 1) * 16);
            asm volatile("cp.async.commit_group;");
            asm volatile("cp.async.wait_group 1;");
        } else {
            asm volatile("cp.async.wait_group 0;");
        }
        __syncthreads();

        const uint32_t* Ah = gsm + s * 4 * G5PLANE;
        const uint32_t* Al = Ah + G5PLANE;
        const uint32_t* Bh = Ah + 2 * G5PLANE;
        const uint32_t* Bl = Ah + 3 * G5PLANE;

#pragma unroll
        for (int ks = 0; ks < 2; ks++) {
            const int kb = ks * 8;
            uint32_t bhv[4][2], blv[4][2];
#pragma unroll
            for (int nt = 0; nt < 4; nt++) {
                int n = wn + nt * 8 + g;
                bhv[nt][0] = Bh[n * GKP + kb + tg];
                bhv[nt][1] = Bh[n * GKP + kb + tg + 4];
                blv[nt][0] = Bl[n * GKP + kb + tg];
                blv[nt][1] = Bl[n * GKP + kb + tg + 4];
            }
#pragma unroll
            for (int mt = 0; mt < 4; mt++) {
                int m = wm + mt * 16 + g;
                uint32_t ah[4], al[4];
                ah[0] = Ah[m * GKP + kb + tg];
                ah[1] = Ah[(m + 8) * GKP + kb + tg];
                ah[2] = Ah[m * GKP + kb + tg + 4];
                ah[3] = Ah[(m + 8) * GKP + kb + tg + 4];
                al[0] = Al[m * GKP + kb + tg];
                al[1] = Al[(m + 8) * GKP + kb + tg];
                al[2] = Al[m * GKP + kb + tg + 4];
                al[3] = Al[(m + 8) * GKP + kb + tg + 4];
#pragma unroll
                for (int nt = 0; nt < 4; nt++) {
                    mma16(acc[mt][nt], ah[0], ah[1], ah[2], ah[3], bhv[nt][0], bhv[nt][1]);
                    mma16(acc[mt][nt], ah[0], ah[1], ah[2], ah[3], blv[nt][0], blv[nt][1]);
                    mma16(acc[mt][nt], al[0], al[1], al[2], al[3], bhv[nt][0], bhv[nt][1]);
                }
            }
        }
        __syncthreads();
    }

#pragma unroll
    for (int mt = 0; mt < 4; mt++) {
        int row = bm + wm + mt * 16 + g;
#pragma unroll
        for (int nt = 0; nt < 4; nt++) {
            int col = bn + wn + nt * 8 + tg * 2;
            float b0 = bias[col], b1 = bias[col + 1];
            float2 v0 = make_float2(acc[mt][nt][0] + b0, acc[mt][nt][1] + b1);
            float2 v1 = make_float2(acc[mt][nt][2] + b0, acc[mt][nt][3] + b1);
            *(float2*)(C + (size_t)row * N + col) = v0;
            *(float2*)(C + (size_t)(row + 8) * N + col) = v1;
        }
    }
}

// ---------------------------------------------------------------------------
// Fused attention (R12-proven): writes unnormalized P (.cs) + 1/rowsum;
// X written directly as hi/lo planes; zero-fill upper tiles at the tail.
// ---------------------------------------------------------------------------
#define IT 128
#define JT 32
#define FA_SMEM_BYTES 86016

__global__ __launch_bounds__(256) void fused_attn(float* __restrict__ attn)
{
    extern __shared__ uint32_t smu[];
    uint32_t* Qh = smu;
    uint32_t* Ql = smu + 4608;
    uint32_t* Kh = smu + 9216;
    uint32_t* Kl = smu + 10368;
    float*    Vs = (float*)(smu + 11520);
    uint32_t* Vh = smu + 13696;
    uint32_t* Vl = smu + 14976;
    uint32_t* Ph = smu + 16256;
    uint32_t* Pl = smu + 18816;
    float*    rs = (float*)(smu + 21376);

    const int bh = blockIdx.z, b = bh >> 4, h = bh & 15;
    const int itile = (gridDim.x - 1) - blockIdx.x;
    const int i0 = itile * IT;
    const int tid = threadIdx.x, lane = tid & 31, warp = tid >> 5;
    const int g = lane >> 2, tg = lane & 3;
    const int wm = warp * 16;
    const int wmv = (warp >> 1) * 32, wnv = (warp & 1) * 32;

#pragma unroll
    for (int u = 0; u < 8; u++) {
        int idx = tid + u * 256;
        int row = idx >> 4, c4 = (idx & 15) * 4;
        float4 v = *(const float4*)(g_Qp + (size_t)(b * SS + i0 + row) * DD + h * DK + c4);
        uint32_t h0, l0, h1, l1;
        bfsplit2(v.x, v.y, h0, l0);
        bfsplit2(v.z, v.w, h1, l1);
        *(uint2*)&Qh[row * 36 + (c4 >> 1)] = make_uint2(h0, h1);
        *(uint2*)&Ql[row * 36 + (c4 >> 1)] = make_uint2(l0, l1);
    }

    float acc_v[2][4][4];
#pragma unroll
    for (int mt = 0; mt < 2; mt++)
#pragma unroll
        for (int nt = 0; nt < 4; nt++)
#pragma unroll
            for (int r = 0; r < 4; r++) acc_v[mt][nt][r] = 0.f;
    float rs0 = 0.f, rs1 = 0.f;

    const int krow0 = tid >> 4, kc4 = (tid & 15) * 4;
    const int krow1 = krow0 + 16;

    const int nj = (i0 >> 5) + 4;
    float4 kv[4];
    kv[0] = *(const float4*)(g_Kp + (size_t)(b * SS + krow0) * DD + h * DK + kc4);
    kv[1] = *(const float4*)(g_Kp + (size_t)(b * SS + krow1) * DD + h * DK + kc4);
    kv[2] = *(const float4*)(g_Vp + (size_t)(b * SS + krow0) * DD + h * DK + kc4);
    kv[3] = *(const float4*)(g_Vp + (size_t)(b * SS + krow1) * DD + h * DK + kc4);

    const int m0 = wm + g;
    const int gi0 = i0 + m0, gi1 = gi0 + 8;
    float* arow0 = attn + ((size_t)bh * SS + gi0) * SS;
    float* arow1 = attn + ((size_t)bh * SS + gi1) * SS;

    for (int t = 0; t < nj; t++) {
        const int j0 = t * JT;
        __syncthreads();
        {
            uint32_t h0, l0, h1, l1;
            bfsplit2(kv[0].x, kv[0].y, h0, l0);
            bfsplit2(kv[0].z, kv[0].w, h1, l1);
            *(uint2*)&Kh[krow0 * 36 + (kc4 >> 1)] = make_uint2(h0, h1);
            *(uint2*)&Kl[krow0 * 36 + (kc4 >> 1)] = make_uint2(l0, l1);
            bfsplit2(kv[1].x, kv[1].y, h0, l0);
            bfsplit2(kv[1].z, kv[1].w, h1, l1);
            *(uint2*)&Kh[krow1 * 36 + (kc4 >> 1)] = make_uint2(h0, h1);
            *(uint2*)&Kl[krow1 * 36 + (kc4 >> 1)] = make_uint2(l0, l1);
            *(float4*)&Vs[krow0 * 68 + kc4] = kv[2];
            *(float4*)&Vs[krow1 * 68 + kc4] = kv[3];
        }
        __syncthreads();
        if (t + 1 < nj) {
            const int j0n = j0 + JT;
            kv[0] = *(const float4*)(g_Kp + (size_t)(b * SS + j0n + krow0) * DD + h * DK + kc4);
            kv[1] = *(const float4*)(g_Kp + (size_t)(b * SS + j0n + krow1) * DD + h * DK + kc4);
            kv[2] = *(const float4*)(g_Vp + (size_t)(b * SS + j0n + krow0) * DD + h * DK + kc4);
            kv[3] = *(const float4*)(g_Vp + (size_t)(b * SS + j0n + krow1) * DD + h * DK + kc4);
        }

        {
            int n = tid >> 2;
            int jp0 = tid & 3;
#pragma unroll
            for (int e = 0; e < 4; e++) {
                int jp = jp0 + e * 4;
                float v0 = Vs[(2 * jp) * 68 + n];
                float v1 = Vs[(2 * jp + 1) * 68 + n];
                uint32_t hh, ll;
                bfsplit2(v0, v1, hh, ll);
                Vh[n * 20 + jp] = hh;
                Vl[n * 20 + jp] = ll;
            }
        }

        float acc_s[4][4];
#pragma unroll
        for (int nt = 0; nt < 4; nt++)
#pragma unroll
            for (int r = 0; r < 4; r++) acc_s[nt][r] = 0.f;

#pragma unroll
        for (int s4 = 0; s4 < 4; s4++) {
            const int kb = s4 * 8;
            uint32_t ah[4], al[4];
            ah[0] = Qh[m0 * 36 + kb + tg];           al[0] = Ql[m0 * 36 + kb + tg];
            ah[1] = Qh[(m0 + 8) * 36 + kb + tg];     al[1] = Ql[(m0 + 8) * 36 + kb + tg];
            ah[2] = Qh[m0 * 36 + kb + tg + 4];       al[2] = Ql[m0 * 36 + kb + tg + 4];
            ah[3] = Qh[(m0 + 8) * 36 + kb + tg + 4]; al[3] = Ql[(m0 + 8) * 36 + kb + tg + 4];
#pragma unroll
            for (int nt = 0; nt < 4; nt++) {
                int n = nt * 8 + g;
                uint32_t bh0 = Kh[n * 36 + kb + tg];
                uint32_t bh1 = Kh[n * 36 + kb + tg + 4];
                uint32_t bl0 = Kl[n * 36 + kb + tg];
                uint32_t bl1 = Kl[n * 36 + kb + tg + 4];
                mma16(acc_s[nt], ah[0], ah[1], ah[2], ah[3], bh0, bh1);
                mma16(acc_s[nt], ah[0], ah[1], ah[2], ah[3], bl0, bl1);
                mma16(acc_s[nt], al[0], al[1], al[2], al[3], bh0, bh1);
            }
        }

        const bool needmask = (j0 + JT - 1 > gi0);
#pragma unroll
        for (int nt = 0; nt < 4; nt++) {
            int cl = nt * 8 + tg * 2;
            int c = j0 + cl;
            float p00 = __expf(acc_s[nt][0] * 0.125f);
            float p01 = __expf(acc_s[nt][1] * 0.125f);
            float p10 = __expf(acc_s[nt][2] * 0.125f);
            float p11 = __expf(acc_s[nt][3] * 0.125f);
            if (needmask) {
                if (c     > gi0) p00 = 0.f;
                if (c + 1 > gi0) p01 = 0.f;
                if (c     > gi1) p10 = 0.f;
                if (c + 1 > gi1) p11 = 0.f;
            }
            rs0 += p00 + p01;
            rs1 += p10 + p11;
            __stcs((float2*)(arow0 + c), make_float2(p00, p01));
            __stcs((float2*)(arow1 + c), make_float2(p10, p11));
            uint32_t hh, ll;
            bfsplit2(p00, p01, hh, ll);
            Ph[m0 * 20 + nt * 4 + tg] = hh;
            Pl[m0 * 20 + nt * 4 + tg] = ll;
            bfsplit2(p10, p11, hh, ll);
            Ph[(m0 + 8) * 20 + nt * 4 + tg] = hh;
            Pl[(m0 + 8) * 20 + nt * 4 + tg] = ll;
        }
        __syncthreads();

#pragma unroll
        for (int s2 = 0; s2 < 2; s2++) {
            const int kb = s2 * 8;
            uint32_t pah[2][4], pal[2][4];
#pragma unroll
            for (int mt = 0; mt < 2; mt++) {
                int m = wmv + mt * 16 + g;
                pah[mt][0] = Ph[m * 20 + kb + tg];
                pah[mt][1] = Ph[(m + 8) * 20 + kb + tg];
                pah[mt][2] = Ph[m * 20 + kb + tg + 4];
                pah[mt][3] = Ph[(m + 8) * 20 + kb + tg + 4];
                pal[mt][0] = Pl[m * 20 + kb + tg];
                pal[mt][1] = Pl[(m + 8) * 20 + kb + tg];
                pal[mt][2] = Pl[m * 20 + kb + tg + 4];
                pal[mt][3] = Pl[(m + 8) * 20 + kb + tg + 4];
            }
#pragma unroll
            for (int nt = 0; nt < 4; nt++) {
                int n = wnv + nt * 8 + g;
                uint32_t vh0 = Vh[n * 20 + kb + tg];
                uint32_t vh1 = Vh[n * 20 + kb + tg + 4];
                uint32_t vl0 = Vl[n * 20 + kb + tg];
                uint32_t vl1 = Vl[n * 20 + kb + tg + 4];
#pragma unroll
                for (int mt = 0; mt < 2; mt++) {
                    mma16(acc_v[mt][nt], pah[mt][0], pah[mt][1], pah[mt][2], pah[mt][3], vh0, vh1);
                    mma16(acc_v[mt][nt], pah[mt][0], pah[mt][1], pah[mt][2], pah[mt][3], vl0, vl1);
                    mma16(acc_v[mt][nt], pal[mt][0], pal[mt][1], pal[mt][2], pal[mt][3], vh0, vh1);
                }
            }
        }
    }

    rs0 += __shfl_xor_sync(0xffffffffu, rs0, 1);
    rs0 += __shfl_xor_sync(0xffffffffu, rs0, 2);
    rs1 += __shfl_xor_sync(0xffffffffu, rs1, 1);
    rs1 += __shfl_xor_sync(0xffffffffu, rs1, 2);
    if (tg == 0) { rs[m0] = rs0; rs[m0 + 8] = rs1; }
    __syncthreads();
    if (tid < 128) g_rinv[(size_t)bh * SS + i0 + tid] = 1.0f / rs[tid];

    const int Kp2 = DD / 2;
#pragma unroll
    for (int mt = 0; mt < 2; mt++) {
        int r0 = wmv + mt * 16 + g, r1 = r0 + 8;
        float inv0 = 1.0f / rs[r0], inv1 = 1.0f / rs[r1];
        size_t w0 = (size_t)(b * SS + i0 + r0) * Kp2 + (h * DK + wnv) / 2;
        size_t w1 = (size_t)(b * SS + i0 + r1) * Kp2 + (h * DK + wnv) / 2;
#pragma unroll
        for (int nt = 0; nt < 4; nt++) {
            int cp = nt * 4 + tg;
            uint32_t hh, ll;
            bfsplit2(acc_v[mt][nt][0] * inv0, acc_v[mt][nt][1] * inv0, hh, ll);
            g_xh[w0 + cp] = hh; g_xl[w0 + cp] = ll;
            bfsplit2(acc_v[mt][nt][2] * inv1, acc_v[mt][nt][3] * inv1, hh, ll);
            g_xh[w1 + cp] = hh; g_xl[w1 + cp] = ll;
        }
    }

    const int jend = i0 + IT;
    const int zw4 = (SS - jend) >> 2;
    if (zw4 > 0) {
        float4 z = make_float4(0.f, 0.f, 0.f, 0.f);
        for (int r = warp; r < IT; r += 8) {
            float* rowp = attn + ((size_t)bh * SS + i0 + r) * SS + jend;
            for (int cq = lane; cq < zw4; cq += 32)
                __stcs((float4*)(rowp + cq * 4), z);
        }
    }
}

// ---------------------------------------------------------------------------
// Normalize v2: tile-parallel. Grid (jt=16, it=16, bh=64); 128x128 tile per
// block; jt > it exits (region is exact zeros). Diagonal tiles need no mask
// (masked entries are exact 0; 0 * inv = 0). 16 coalesced float4/thread.
// ---------------------------------------------------------------------------
__global__ __launch_bounds__(256) void normalize_attn2(float* __restrict__ attn)
{
    const int jt = blockIdx.x, it = blockIdx.y, bh = blockIdx.z;
    if (jt > it) return;
    __shared__ float sinv[128];
    const int i0 = it * 128, j0 = jt * 128;
    if (threadIdx.x < 128)
        sinv[threadIdx.x] = g_rinv[(size_t)bh * SS + i0 + threadIdx.x];
    __syncthreads();

    float4* base = (float4*)(attn + ((size_t)bh * SS + i0) * SS + j0);
    const int rstride = SS / 4;   // 512 float4 per row
#pragma unroll
    for (int u = 0; u < 16; u++) {
        int idx = u * 256 + threadIdx.x;     // 0..4095
        int r = idx >> 5, cq = idx & 31;     // 32 float4 per tile row
        float inv = sinv[r];
        float4* p = base + (size_t)r * rstride + cq;
        float4 v = __ldcs(p);
        v.x *= inv; v.y *= inv; v.z *= inv; v.w *= inv;
        __stcs(p, v);
    }
}

// ---------------------------------------------------------------------------
extern "C" void kernel_launch(void* const* d_in, const int* in_sizes, int n_in,
                              void* d_out, int out_size)
{
    const float* q    = (const float*)d_in[0];
    const float* k    = (const float*)d_in[1];
    const float* v    = (const float*)d_in[2];
    // d_in[3] = mask (tril) — causality applied analytically
    const float* wq_w = (const float*)d_in[4];
    const float* wq_b = (const float*)d_in[5];
    const float* wk_w = (const float*)d_in[6];
    const float* wk_b = (const float*)d_in[7];
    const float* wv_w = (const float*)d_in[8];
    const float* wv_b = (const float*)d_in[9];
    const float* wo_w = (const float*)d_in[10];
    const float* wo_b = (const float*)d_in[11];

    float* out  = (float*)d_out;
    float* attn = (float*)d_out + OUT0;

    float *qp, *kp, *vp;
    cudaGetSymbolAddress((void**)&qp, g_Qp);
    cudaGetSymbolAddress((void**)&kp, g_Kp);
    cudaGetSymbolAddress((void**)&vp, g_Vp);

    uint32_t *xh, *xl, *wqh, *wql, *wkh, *wkl, *wvh, *wvl, *woh, *wol;
    cudaGetSymbolAddress((void**)&xh, g_xh);   cudaGetSymbolAddress((void**)&xl, g_xl);
    cudaGetSymbolAddress((void**)&wqh, g_wqh); cudaGetSymbolAddress((void**)&wql, g_wql);
    cudaGetSymbolAddress((void**)&wkh, g_wkh); cudaGetSymbolAddress((void**)&wkl, g_wkl);
    cudaGetSymbolAddress((void**)&wvh, g_wvh); cudaGetSymbolAddress((void**)&wvl, g_wvl);
    cudaGetSymbolAddress((void**)&woh, g_woh); cudaGetSymbolAddress((void**)&wol, g_wol);

    static bool attr_set = false;
    if (!attr_set) {
        cudaFuncSetAttribute(fused_attn, cudaFuncAttributeMaxDynamicSharedMemorySize,
                             FA_SMEM_BYTES);
        cudaFuncSetAttribute(gemm_nt_tc5, cudaFuncAttributeMaxDynamicSharedMemorySize,
                             G5_SMEM_BYTES);
        cudaFuncSetAttribute(gemm_qkv, cudaFuncAttributeMaxDynamicSharedMemorySize,
                             QKV_SMEM_BYTES);
        attr_set = true;
    }

    const int wqd = DD * DD / 4;

    // weights prep: all 4 matrices in one launch
    SplitArgs sa;
    sa.src[0] = wq_w; sa.hp[0] = wqh; sa.lp[0] = wql;
    sa.src[1] = wk_w; sa.hp[1] = wkh; sa.lp[1] = wkl;
    sa.src[2] = wv_w; sa.hp[2] = wvh; sa.lp[2] = wvl;
    sa.src[3] = wo_w; sa.hp[3] = woh; sa.lp[3] = wol;
    dim3 gsp((wqd + 255) / 256, 4);
    split_pack_w<<<gsp, 256>>>(sa, wqd);

    // QKV projections, one batched launch
    dim3 gqkv(DD / 128, MM / 128, 3);      // (8, 64, 3)
    gemm_qkv<<<gqkv, 256, QKV_SMEM_BYTES>>>(q, k, v, wq_b, wk_b, wv_b, qp, kp, vp);

    dim3 gfa(SS / IT, 1, BB * HH);         // (16, 1, 64)
    fused_attn<<<gfa, 256, FA_SMEM_BYTES>>>(attn);

    dim3 gnorm(SS / 128, SS / 128, BB * HH);  // (16, 16, 64)
    normalize_attn2<<<gnorm, 256>>>(attn);

    dim3 gproj(DD / 128, MM / 128);        // (8, 64)
    gemm_nt_tc5<<<gproj, 256, G5_SMEM_BYTES>>>(xh, xl, woh, wol, wo_b, out, DD, DD);
}